// round 15
// baseline (speedup 1.0000x reference)
#include <cuda_runtime.h>
#include <cstdint>

#define BATCH 16384
#define NNEG 10
#define NROWS 13          // v, u1, u2, 10 negatives
#define NDIM4 32          // 128 floats = 32 float4 per row
#define WARPS_PER_BLOCK 4
#define THREADS (WARPS_PER_BLOCK * 32)

// fast stable softplus: log(1+exp(x)) = max(x,0) + log(1 + exp(-|x|))
__device__ __forceinline__ float softplus_f(float x) {
    return fmaxf(x, 0.0f) + __logf(1.0f + __expf(-fabsf(x)));
}

__device__ __forceinline__ float warp_sum(float x) {
    #pragma unroll
    for (int off = 16; off > 0; off >>= 1)
        x += __shfl_xor_sync(0xFFFFFFFFu, x, off);
    return x;
}

__device__ __forceinline__ void cp_async16(uint32_t dst_smem, const void* src_gmem) {
    // 16B cp.async, L2-only (.cg): no result registers, no L1 pollution.
    asm volatile("cp.async.cg.shared.global [%0], [%1], 16;"
                 :: "r"(dst_smem), "l"(src_gmem));
}

__global__ __launch_bounds__(THREADS, 8) void all2vec_kernel(
    const int*    __restrict__ pos_v,
    const int*    __restrict__ pos_u,
    const int*    __restrict__ neg,
    const float*  __restrict__ weights,
    const float4* __restrict__ emb,      // [N_VERTICES * 32] float4
    const float4* __restrict__ emb_ctx,  // [N_VERTICES * 32] float4
    float*        __restrict__ out)      // [2 * BATCH]: score_1 then score_2
{
    // staging: each warp parks its 13 rows (13 x 512B) in smem via cp.async,
    // so all 13 gathers are in flight at once with zero register pressure.
    __shared__ float4 stage[WARPS_PER_BLOCK][NROWS][NDIM4];

    const int w    = threadIdx.x >> 5;
    const int lane = threadIdx.x & 31;
    const int b    = blockIdx.x * WARPS_PER_BLOCK + w;
    if (b >= BATCH) return;

    // --- indices (broadcast loads; independent, issued together) ---
    const int iv = pos_v[b];
    const int iu = pos_u[b];
    int ineg[NNEG];
    #pragma unroll
    for (int k = 0; k < NNEG; k++) ineg[k] = neg[b * NNEG + k];

    // --- issue all 13 row-gathers as cp.async (52 lines outstanding/warp) ---
    uint32_t sbase = (uint32_t)__cvta_generic_to_shared(&stage[w][0][lane]);
    const uint32_t srow = NDIM4 * sizeof(float4);  // 512B row stride

    cp_async16(sbase + 0 * srow, &emb    [(size_t)iv * NDIM4 + lane]);
    cp_async16(sbase + 1 * srow, &emb    [(size_t)iu * NDIM4 + lane]);
    cp_async16(sbase + 2 * srow, &emb_ctx[(size_t)iu * NDIM4 + lane]);
    #pragma unroll
    for (int k = 0; k < NNEG; k++)
        cp_async16(sbase + (3 + k) * srow, &emb_ctx[(size_t)ineg[k] * NDIM4 + lane]);

    asm volatile("cp.async.wait_all;" ::: "memory");
    // each lane reads back only its own 16B slices -> no cross-lane sync needed

    // --- per-lane partial dots (read rows back from smem) ---
    const float4 v  = stage[w][0][lane];
    const float4 u1 = stage[w][1][lane];
    const float4 u2 = stage[w][2][lane];

    float d1 = v.x * u1.x + v.y * u1.y + v.z * u1.z + v.w * u1.w;
    float d2 = v.x * u2.x + v.y * u2.y + v.z * u2.z + v.w * u2.w;
    float dn[NNEG];
    #pragma unroll
    for (int k = 0; k < NNEG; k++) {
        const float4 nv = stage[w][3 + k][lane];
        dn[k] = v.x * nv.x + v.y * nv.y + v.z * nv.z + v.w * nv.w;
    }

    // --- warp reductions ---
    d1 = warp_sum(d1);
    d2 = warp_sum(d2);
    #pragma unroll
    for (int k = 0; k < NNEG; k++)
        dn[k] = warp_sum(dn[k]);

    if (lane == 0) {
        const float wgt = weights[b];
        float negsum = 0.0f;
        #pragma unroll
        for (int k = 0; k < NNEG; k++)
            negsum += softplus_f(dn[k]);
        out[b]         = wgt * (softplus_f(-d1) + negsum);
        out[BATCH + b] = wgt * (softplus_f(-d2) + negsum);
    }
}

extern "C" void kernel_launch(void* const* d_in, const int* in_sizes, int n_in,
                              void* d_out, int out_size) {
    const int*    pos_v   = (const int*)   d_in[0];
    const int*    pos_u   = (const int*)   d_in[1];
    const int*    neg     = (const int*)   d_in[2];
    const float*  weights = (const float*) d_in[3];
    const float4* emb     = (const float4*)d_in[4];
    const float4* emb_ctx = (const float4*)d_in[5];
    float*        out     = (float*)d_out;

    const int blocks = BATCH / WARPS_PER_BLOCK;  // 4096, exact
    all2vec_kernel<<<blocks, THREADS>>>(pos_v, pos_u, neg, weights, emb, emb_ctx, out);
}